// round 3
// baseline (speedup 1.0000x reference)
#include <cuda_runtime.h>
#include <cstdint>

#define N_PAIRS 64000
#define N_ATOMS 16000
#define NF 8
#define NH 100
#define KDIM 900           // (NF+1) * NH : 8 features + 1 bias pseudo-feature

// Scratch in static device globals (no runtime allocation allowed).
__device__ float g_S[(size_t)N_ATOMS * KDIM];   // 57.6 MB accumulator
__device__ float g_Wt[KDIM * NH];               // Wt[f*100+j][i] = W'[f, i*100+j]

// ---------------------------------------------------------------------------
// Build transposed weight matrix Wt[k][i], k = f*100 + j.
// f < 8 -> W[f, i*100 + j]; f == 8 -> b[i*100 + j]  (bias as 9th feature).
// ---------------------------------------------------------------------------
__global__ void prep_wt_kernel(const float* __restrict__ W, const float* __restrict__ b) {
    int tid = blockIdx.x * blockDim.x + threadIdx.x;
    if (tid >= KDIM * NH) return;
    int k = tid / NH;
    int i = tid - k * NH;
    int f = k / NH;
    int j = k - f * NH;
    float v = (f < NF) ? W[f * (NH * NH) + i * NH + j] : b[i * NH + j];
    g_Wt[tid] = v;
}

// ---------------------------------------------------------------------------
// Zero the accumulator.
// ---------------------------------------------------------------------------
__global__ void zero_s_kernel() {
    int tid = blockIdx.x * blockDim.x + threadIdx.x;
    int n4 = (N_ATOMS * KDIM) / 4;
    if (tid < n4) ((float4*)g_S)[tid] = make_float4(0.f, 0.f, 0.f, 0.f);
}

// ---------------------------------------------------------------------------
// Scatter: S[dst, f, j] += pf'[e,f] * atom_features[src, j]
// One thread handles one (pair, 4-wide j chunk): 25 threads per pair.
// Vectorized global reductions (red.global.add.v4.f32, sm_90+).
// ---------------------------------------------------------------------------
__global__ void scatter_kernel(const float* __restrict__ pf,
                               const float* __restrict__ af,
                               const int*   __restrict__ a2p) {
    int idx = blockIdx.x * blockDim.x + threadIdx.x;
    if (idx >= N_PAIRS * 25) return;
    int e = idx / 25;
    int q = idx - e * 25;           // j chunk: covers j = 4q .. 4q+3

    int dst = a2p[2 * e + 0];
    int src = a2p[2 * e + 1];

    float4 v  = *(const float4*)(af + (size_t)src * NH + q * 4);
    float4 c0 = *(const float4*)(pf + (size_t)e * NF);
    float4 c1 = *(const float4*)(pf + (size_t)e * NF + 4);
    float coef[9] = {c0.x, c0.y, c0.z, c0.w, c1.x, c1.y, c1.z, c1.w, 1.0f};

    float* base = g_S + (size_t)dst * KDIM + q * 4;
#pragma unroll
    for (int f = 0; f < 9; f++) {
        float c = coef[f];
        float ax = c * v.x, ay = c * v.y, az = c * v.z, aw = c * v.w;
        asm volatile("red.global.add.v4.f32 [%0], {%1, %2, %3, %4};"
                     :: "l"(base + f * NH), "f"(ax), "f"(ay), "f"(az), "f"(aw)
                     : "memory");
    }
}

// ---------------------------------------------------------------------------
// GEMM: out[16000,100] = S[16000,900] @ Wt[900,100]
// BM=64 rows per block, BK=20 K-chunk, blockDim=(25,8): each thread owns an
// 8-row x 4-col register tile (32 FFMA per k step vs 12 LDS).
// ---------------------------------------------------------------------------
#define BM 64
#define BK 20

__global__ void gemm_kernel(float* __restrict__ out) {
    __shared__ float Ss[BM][BK + 1];     // padded to kill conflicts
    __shared__ float Ws[BK * NH];        // row-major [k][i], contiguous

    int tx = threadIdx.x;                // 0..24  -> cols tx*4 .. tx*4+3
    int ty = threadIdx.y;                // 0..7   -> rows ty*8 .. ty*8+7
    int tid = ty * 25 + tx;              // 0..199
    int row0 = blockIdx.x * BM;

    float acc[8][4];
#pragma unroll
    for (int r = 0; r < 8; r++)
#pragma unroll
        for (int c = 0; c < 4; c++) acc[r][c] = 0.f;

    for (int k0 = 0; k0 < KDIM; k0 += BK) {
        // Load S tile: 64 rows x 20 cols = 320 float4
        for (int t = tid; t < BM * (BK / 4); t += 200) {
            int r = t / 5;
            int q = t - r * 5;
            float4 v = *(const float4*)(g_S + (size_t)(row0 + r) * KDIM + k0 + q * 4);
            Ss[r][q * 4 + 0] = v.x;
            Ss[r][q * 4 + 1] = v.y;
            Ss[r][q * 4 + 2] = v.z;
            Ss[r][q * 4 + 3] = v.w;
        }
        // Load W tile: contiguous 2000 floats = 500 float4
        for (int t = tid; t < (BK * NH) / 4; t += 200) {
            ((float4*)Ws)[t] = *(const float4*)(g_Wt + (size_t)k0 * NH + t * 4);
        }
        __syncthreads();

#pragma unroll
        for (int k = 0; k < BK; k++) {
            float4 w = *(const float4*)&Ws[k * NH + tx * 4];
#pragma unroll
            for (int r = 0; r < 8; r++) {
                float s = Ss[ty * 8 + r][k];
                acc[r][0] += s * w.x;
                acc[r][1] += s * w.y;
                acc[r][2] += s * w.z;
                acc[r][3] += s * w.w;
            }
        }
        __syncthreads();
    }

#pragma unroll
    for (int r = 0; r < 8; r++) {
        float4 o = make_float4(acc[r][0], acc[r][1], acc[r][2], acc[r][3]);
        *(float4*)(out + (size_t)(row0 + ty * 8 + r) * NH + tx * 4) = o;
    }
}

// ---------------------------------------------------------------------------
extern "C" void kernel_launch(void* const* d_in, const int* in_sizes, int n_in,
                              void* d_out, int out_size) {
    const float* pf  = (const float*)d_in[0];   // [64000, 8]
    const float* af  = (const float*)d_in[1];   // [16000, 100]
    const int*   a2p = (const int*)  d_in[2];   // [64000, 2]
    const float* W   = (const float*)d_in[3];   // [8, 10000]
    const float* b   = (const float*)d_in[4];   // [10000]
    float* out = (float*)d_out;                 // [16000, 100]

    prep_wt_kernel<<<(KDIM * NH + 255) / 256, 256>>>(W, b);
    zero_s_kernel<<<((N_ATOMS * KDIM) / 4 + 255) / 256, 256>>>();
    scatter_kernel<<<(N_PAIRS * 25 + 127) / 128, 128>>>(pf, af, a2p);
    gemm_kernel<<<N_ATOMS / BM, dim3(25, 8)>>>(out);
}